// round 6
// baseline (speedup 1.0000x reference)
#include <cuda_runtime.h>
#include <cuda_bf16.h>
#include <mma.h>
#include <math.h>
#include <stdint.h>

// ---------------- model constants ----------------
#define D_MODEL 768
#define N_LAYER 4
#define D_STATE 16
#define D_CONV 4
#define DT_RANK 48
#define D_INNER 1536
#define B_SZ 2
#define L_SEQ 1024
#define N_MELS 80
#define M_ROWS (B_SZ * L_SEQ)              // 2048
#define XDBL_COLS (DT_RANK + 2 * D_STATE)  // 80

// ---------------- scratch (device globals; no runtime alloc) ----------------
__device__ float g_x[M_ROWS * D_MODEL];        // residual stream
__device__ float g_h[M_ROWS * D_MODEL];        // out_proj result
__device__ float g_xz[M_ROWS * 2 * D_INNER];   // in_proj output
__device__ float g_xi[M_ROWS * D_INNER];       // conv+silu (u) fp32 for scan
__device__ float g_xdbl[M_ROWS * XDBL_COLS];   // x_proj output fp32
__device__ float g_delta[M_ROWS * D_INNER];    // softplus(dt)
// split-bf16 staging: A operands (activations) and B operands (weights)
__device__ __nv_bfloat16 g_Ah[M_ROWS * D_INNER];
__device__ __nv_bfloat16 g_Al[M_ROWS * D_INNER];
__device__ __nv_bfloat16 g_Bh[D_MODEL * 2 * D_INNER];
__device__ __nv_bfloat16 g_Bl[D_MODEL * 2 * D_INNER];

__device__ __forceinline__ void split_bf16(float v, __nv_bfloat16& hi, __nv_bfloat16& lo) {
    __nv_bfloat16 h = __float2bfloat16(v);
    float r = v - __bfloat162float(h);
    hi = h;
    lo = __float2bfloat16(r);
}

__device__ __forceinline__ void cpa16(uint32_t dst, const void* src, int valid) {
    asm volatile("cp.async.ca.shared.global [%0], [%1], 16, %2;"
                 :: "r"(dst), "l"(src), "r"(valid));
}

// ---------------- WMMA bf16 GEMM, pre-split inputs, cp.async pipeline -------
// C[M,N] = (Ah+Al)[M,K] * (Bh+Bl)[K,N]  (3-product split, fp32 accumulate)
// Block 128x128, BK=32, 8 warps (2x4), warp tile 64x32.
__global__ __launch_bounds__(256, 1)
void wmma_gemm_bf16(int M, int N, int K,
                    const __nv_bfloat16* __restrict__ Ah,
                    const __nv_bfloat16* __restrict__ Al, int lda,
                    const __nv_bfloat16* __restrict__ Bh,
                    const __nv_bfloat16* __restrict__ Bl, int ldb,
                    float* __restrict__ C, int ldc)
{
    using namespace nvcuda;
    constexpr int SA = 40;       // A row stride (bf16 elems), 80 B
    constexpr int SB = 136;      // B row stride, 272 B
    constexpr int OFF_AH = 0;
    constexpr int OFF_AL = 128 * SA * 2;            // 10240
    constexpr int OFF_BH = 2 * 128 * SA * 2;        // 20480
    constexpr int OFF_BL = OFF_BH + 32 * SB * 2;    // 29184
    constexpr int STAGE  = OFF_BL + 32 * SB * 2;    // 37888

    extern __shared__ char sm[];
    const uint32_t smb = (uint32_t)__cvta_generic_to_shared(sm);

    const int t    = threadIdx.x;
    const int warp = t >> 5;
    const int wm   = warp >> 2;
    const int wn   = warp & 3;
    const int row0 = blockIdx.y * 128;
    const int col0 = blockIdx.x * 128;
    const int KT   = (K + 31) / 32;

    wmma::fragment<wmma::accumulator, 16, 16, 16, float> acc[4][2];
#pragma unroll
    for (int i = 0; i < 4; i++)
#pragma unroll
        for (int j = 0; j < 2; j++) wmma::fill_fragment(acc[i][j], 0.0f);

    // ---- async tile loaders (8 cp.async / thread / stage) ----
    auto issueA = [&](int st, int k0, const __nv_bfloat16* P, uint32_t off) {
#pragma unroll
        for (int ss = 0; ss < 2; ss++) {
            int seg = t + ss * 256;           // 0..511
            int row = seg >> 2, sk = seg & 3;
            int kk = k0 + sk * 8;
            int valid = (K - kk) * 2;
            valid = valid < 0 ? 0 : (valid > 16 ? 16 : valid);
            const __nv_bfloat16* src = P + (long)(row0 + row) * lda + (valid ? kk : 0);
            cpa16(smb + st * STAGE + off + row * (SA * 2) + sk * 16, src, valid);
        }
    };
    auto issueB = [&](int st, int k0, const __nv_bfloat16* P, uint32_t off) {
#pragma unroll
        for (int ss = 0; ss < 2; ss++) {
            int seg = t + ss * 256;           // 0..511
            int row = seg >> 4, sk = seg & 15;
            int nn = col0 + sk * 8;
            int valid = (k0 + row < K) ? (N - nn) * 2 : 0;
            valid = valid < 0 ? 0 : (valid > 16 ? 16 : valid);
            const __nv_bfloat16* src = P + (long)(k0 + row) * ldb + (valid ? nn : 0);
            cpa16(smb + st * STAGE + off + row * (SB * 2) + sk * 16, src, valid);
        }
    };
    auto issue_stage = [&](int st, int k0) {
        issueA(st, k0, Ah, OFF_AH);
        issueA(st, k0, Al, OFF_AL);
        issueB(st, k0, Bh, OFF_BH);
        issueB(st, k0, Bl, OFF_BL);
    };

    issue_stage(0, 0);
    asm volatile("cp.async.commit_group;" ::: "memory");

    for (int kt = 0; kt < KT; kt++) {
        if (kt + 1 < KT) issue_stage((kt + 1) & 1, (kt + 1) * 32);
        asm volatile("cp.async.commit_group;" ::: "memory");
        asm volatile("cp.async.wait_group 1;" ::: "memory");
        __syncthreads();

        const char* buf = sm + (kt & 1) * STAGE;
        const __nv_bfloat16* pAh = (const __nv_bfloat16*)(buf + OFF_AH);
        const __nv_bfloat16* pAl = (const __nv_bfloat16*)(buf + OFF_AL);
        const __nv_bfloat16* pBh = (const __nv_bfloat16*)(buf + OFF_BH);
        const __nv_bfloat16* pBl = (const __nv_bfloat16*)(buf + OFF_BL);

#pragma unroll
        for (int ks = 0; ks < 2; ks++) {
            wmma::fragment<wmma::matrix_b, 16, 16, 16, __nv_bfloat16, wmma::row_major> fbh[2], fbl[2];
#pragma unroll
            for (int j = 0; j < 2; j++) {
                wmma::load_matrix_sync(fbh[j], pBh + (ks * 16) * SB + wn * 32 + j * 16, SB);
                wmma::load_matrix_sync(fbl[j], pBl + (ks * 16) * SB + wn * 32 + j * 16, SB);
            }
#pragma unroll
            for (int i = 0; i < 4; i++) {
                wmma::fragment<wmma::matrix_a, 16, 16, 16, __nv_bfloat16, wmma::row_major> fah, fal;
                wmma::load_matrix_sync(fah, pAh + (wm * 64 + i * 16) * SA + ks * 16, SA);
                wmma::load_matrix_sync(fal, pAl + (wm * 64 + i * 16) * SA + ks * 16, SA);
#pragma unroll
                for (int j = 0; j < 2; j++) {
                    wmma::mma_sync(acc[i][j], fah, fbh[j], acc[i][j]);
                    wmma::mma_sync(acc[i][j], fah, fbl[j], acc[i][j]);
                    wmma::mma_sync(acc[i][j], fal, fbh[j], acc[i][j]);
                }
            }
        }
        __syncthreads();   // compute done before next stage overwrites buffer
    }

    // ---- epilogue ----
#pragma unroll
    for (int i = 0; i < 4; i++)
#pragma unroll
        for (int j = 0; j < 2; j++) {
            int gm = row0 + wm * 64 + i * 16;
            int gn = col0 + wn * 32 + j * 16;
            if (gn + 16 <= N)
                wmma::store_matrix_sync(C + (long)gm * ldc + gn, acc[i][j],
                                        ldc, wmma::mem_row_major);
        }
}

// ---------------- split helpers ----------------
__global__ void split_arr_kernel(const float* __restrict__ in,
                                 __nv_bfloat16* __restrict__ hi,
                                 __nv_bfloat16* __restrict__ lo, int count)
{
    int i = blockIdx.x * blockDim.x + threadIdx.x;
    if (i < count) {
        __nv_bfloat16 h, l;
        split_bf16(in[i], h, l);
        hi[i] = h; lo[i] = l;
    }
}

// pack xdbl[:, :48] -> split bf16 [2048 x 48]
__global__ void split_xdbl48_kernel(void)
{
    int i = blockIdx.x * blockDim.x + threadIdx.x;
    if (i < M_ROWS * DT_RANK) {
        int r = i / DT_RANK, c = i % DT_RANK;
        __nv_bfloat16 h, l;
        split_bf16(g_xdbl[r * XDBL_COLS + c], h, l);
        g_Ah[i] = h; g_Al[i] = l;
    }
}

// ---------------- elementwise / small kernels ----------------
__global__ void embed_kernel(const int* __restrict__ ids,
                             const float* __restrict__ emb)
{
    int row = blockIdx.x;
    int id = ids[row];
    for (int c = threadIdx.x; c < D_MODEL; c += blockDim.x)
        g_x[row * D_MODEL + c] = emb[(long)id * D_MODEL + c];
}

// rmsnorm fused with split-bf16 output (feeds GEMM A directly)
__global__ void rmsnorm_split_kernel(const float* __restrict__ x,
                                     const float* __restrict__ w)
{
    __shared__ float red[256];
    int row = blockIdx.x;
    const float* xr = x + row * D_MODEL;
    float s = 0.0f;
    for (int c = threadIdx.x; c < D_MODEL; c += blockDim.x) {
        float v = xr[c];
        s += v * v;
    }
    red[threadIdx.x] = s;
    __syncthreads();
    for (int off = 128; off > 0; off >>= 1) {
        if (threadIdx.x < off) red[threadIdx.x] += red[threadIdx.x + off];
        __syncthreads();
    }
    float scale = rsqrtf(red[0] / (float)D_MODEL + 1e-5f);
    for (int c = threadIdx.x; c < D_MODEL; c += blockDim.x) {
        __nv_bfloat16 h, l;
        split_bf16(xr[c] * scale * w[c], h, l);
        g_Ah[row * D_MODEL + c] = h;
        g_Al[row * D_MODEL + c] = l;
    }
}

// conv+silu fused with split output (xi fp32 kept for scan)
__global__ void conv_silu_kernel(const float* __restrict__ cw,
                                 const float* __restrict__ cb)
{
    int i = blockIdx.x * blockDim.x + threadIdx.x;
    if (i >= M_ROWS * D_INNER) return;
    int row = i / D_INNER;
    int d = i % D_INNER;
    int b = row / L_SEQ;
    int l = row % L_SEQ;
    float acc = cb[d];
#pragma unroll
    for (int k = 0; k < D_CONV; k++) {
        int ll = l + k - (D_CONV - 1);
        if (ll >= 0)
            acc = fmaf(g_xz[(long)(b * L_SEQ + ll) * (2 * D_INNER) + d],
                       cw[d * D_CONV + k], acc);
    }
    float sg = 1.0f / (1.0f + __expf(-acc));
    float v = acc * sg;
    g_xi[i] = v;
    __nv_bfloat16 h, lo;
    split_bf16(v, h, lo);
    g_Ah[i] = h; g_Al[i] = lo;
}

__global__ void bias_softplus_kernel(const float* __restrict__ bias)
{
    int i = blockIdx.x * blockDim.x + threadIdx.x;
    if (i >= M_ROWS * D_INNER) return;
    int d = i % D_INNER;
    float v = g_delta[i] + bias[d];
    float r = (v > 30.0f) ? v : log1pf(__expf(v));
    g_delta[i] = r;
}

__global__ void residual_add_kernel(void)
{
    int i = blockIdx.x * blockDim.x + threadIdx.x;
    if (i < M_ROWS * D_MODEL) g_x[i] += g_h[i];
}

// ---------------- selective scan (chunked parallel prefix, R5) -------------
// Writes gated y directly as split bf16 into g_Ah/g_Al (A of out_proj GEMM).
__global__ __launch_bounds__(256)
void scan_kernel(const float* __restrict__ A_log,
                 const float* __restrict__ Dp)
{
    __shared__ float sTot[16][17];
    __shared__ float pTot[16][17];

    const int tid = threadIdx.x;
    const int c = tid >> 4;
    const int n = tid & 15;
    const int bd = blockIdx.x;
    const int b = bd / D_INNER;
    const int d = bd % D_INNER;

    const float A_dn = -__expf(A_log[d * D_STATE + n]);
    const int CH = L_SEQ / 16;
    const long rowbase = (long)b * L_SEQ + (long)c * CH;
    const int lg0 = c * CH;

    float sloc = 0.0f;
    for (int i = 0; i < CH; i++) {
        float dt = g_delta[(rowbase + i) * D_INNER + d];
        float a = fmaxf(dt * A_dn, -20.0f);
        if (lg0 + i > 0) sloc += a;
    }
    sTot[n][c] = sloc;
    __syncthreads();
    float soff = 0.0f;
#pragma unroll
    for (int cc = 0; cc < 16; cc++)
        if (cc < c) soff += sTot[n][cc];

    sloc = 0.0f;
    float Ploc = 0.0f;
    for (int i = 0; i < CH; i++) {
        long row = rowbase + i;
        float dt = g_delta[row * D_INNER + d];
        float u  = g_xi[row * D_INNER + d];
        float Bn = g_xdbl[row * XDBL_COLS + DT_RANK + n];
        float a = fmaxf(dt * A_dn, -20.0f);
        if (lg0 + i > 0) sloc += a;
        float e = __expf(soff + sloc);
        Ploc += __fdividef(dt * u * Bn, e + 1e-12f);
    }
    pTot[n][c] = Ploc;
    __syncthreads();
    float Poff = 0.0f;
#pragma unroll
    for (int cc = 0; cc < 16; cc++)
        if (cc < c) Poff += pTot[n][cc];

    const float Dd = Dp[d];

    sloc = 0.0f;
    Ploc = 0.0f;
    for (int i = 0; i < CH; i++) {
        long row = rowbase + i;
        float dt = g_delta[row * D_INNER + d];
        float u  = g_xi[row * D_INNER + d];
        float Bn = g_xdbl[row * XDBL_COLS + DT_RANK + n];
        float Cn = g_xdbl[row * XDBL_COLS + DT_RANK + D_STATE + n];
        float a = fmaxf(dt * A_dn, -20.0f);
        if (lg0 + i > 0) sloc += a;
        float e = __expf(soff + sloc);
        Ploc += __fdividef(dt * u * Bn, e + 1e-12f);
        float x = (Poff + Ploc) * e;
        float yp = x * Cn;
#pragma unroll
        for (int off = 8; off >= 1; off >>= 1)
            yp += __shfl_xor_sync(0xffffffffu, yp, off, 16);
        if (n == 0) {
            float r = g_xz[row * (2 * D_INNER) + D_INNER + d];
            float sr = r / (1.0f + __expf(-r));
            float yv = (yp + u * Dd) * sr;
            __nv_bfloat16 h, l;
            split_bf16(yv, h, l);
            g_Ah[row * D_INNER + d] = h;
            g_Al[row * D_INNER + d] = l;
        }
    }
}

// ---------------- host side ----------------
static inline void* sym(const void* s)
{
    void* p = nullptr;
    cudaGetSymbolAddress(&p, s);
    return p;
}

#define GEMM_SMEM (2 * 37888)

static void launch_gemm(int M, int N, int K,
                        const __nv_bfloat16* Ah, const __nv_bfloat16* Al, int lda,
                        const __nv_bfloat16* Bh, const __nv_bfloat16* Bl, int ldb,
                        float* C, int ldc)
{
    dim3 grid((N + 127) / 128, M / 128);
    wmma_gemm_bf16<<<grid, 256, GEMM_SMEM>>>(M, N, K, Ah, Al, lda, Bh, Bl, ldb, C, ldc);
}

extern "C" void kernel_launch(void* const* d_in, const int* in_sizes, int n_in,
                              void* d_out, int out_size)
{
    const int*   input_ids = (const int*)  d_in[0];
    const float* embedding = (const float*)d_in[1];
    const float* rms_w     = (const float*)d_in[2];
    const float* in_proj_w = (const float*)d_in[3];
    const float* conv_w    = (const float*)d_in[4];
    const float* conv_b    = (const float*)d_in[5];
    const float* x_proj_w  = (const float*)d_in[6];
    const float* dt_proj_w = (const float*)d_in[7];
    const float* dt_proj_b = (const float*)d_in[8];
    const float* A_log     = (const float*)d_in[9];
    const float* D_param   = (const float*)d_in[10];
    const float* out_proj_w= (const float*)d_in[11];
    const float* norm_f_w  = (const float*)d_in[12];
    const float* head_w    = (const float*)d_in[13];
    float* out = (float*)d_out;

    float* px     = (float*)sym(g_x);
    float* pxz    = (float*)sym(g_xz);
    float* pxdbl  = (float*)sym(g_xdbl);
    float* pdelta = (float*)sym(g_delta);
    float* ph     = (float*)sym(g_h);
    __nv_bfloat16* pAh = (__nv_bfloat16*)sym(g_Ah);
    __nv_bfloat16* pAl = (__nv_bfloat16*)sym(g_Al);
    __nv_bfloat16* pBh = (__nv_bfloat16*)sym(g_Bh);
    __nv_bfloat16* pBl = (__nv_bfloat16*)sym(g_Bl);

    cudaFuncSetAttribute(wmma_gemm_bf16,
                         cudaFuncAttributeMaxDynamicSharedMemorySize, GEMM_SMEM);

    embed_kernel<<<M_ROWS, 256>>>(input_ids, embedding);

    for (int i = 0; i < N_LAYER; i++) {
        const float* rw  = rms_w     + (long)i * D_MODEL;
        const float* iw  = in_proj_w + (long)i * D_MODEL * 2 * D_INNER;
        const float* cw  = conv_w    + (long)i * D_INNER * D_CONV;
        const float* cb  = conv_b    + (long)i * D_INNER;
        const float* xpw = x_proj_w  + (long)i * D_INNER * XDBL_COLS;
        const float* dtw = dt_proj_w + (long)i * DT_RANK * D_INNER;
        const float* dtb = dt_proj_b + (long)i * D_INNER;
        const float* al  = A_log     + (long)i * D_INNER * D_STATE;
        const float* dp  = D_param   + (long)i * D_INNER;
        const float* ow  = out_proj_w+ (long)i * D_INNER * D_MODEL;

        // 1. rmsnorm -> split A
        rmsnorm_split_kernel<<<M_ROWS, 256>>>(px, rw);

        // 2. split in_proj weights; xz = h @ in_w
        {
            int cnt = D_MODEL * 2 * D_INNER;
            split_arr_kernel<<<(cnt + 255) / 256, 256>>>(iw, pBh, pBl, cnt);
            launch_gemm(M_ROWS, 2 * D_INNER, D_MODEL, pAh, pAl, D_MODEL,
                        pBh, pBl, 2 * D_INNER, pxz, 2 * D_INNER);
        }

        // 3. conv+silu -> xi fp32 + split A
        conv_silu_kernel<<<(M_ROWS * D_INNER + 255) / 256, 256>>>(cw, cb);

        // 4. split x_proj weights; x_dbl = xi @ xp_w
        {
            int cnt = D_INNER * XDBL_COLS;
            split_arr_kernel<<<(cnt + 255) / 256, 256>>>(xpw, pBh, pBl, cnt);
            launch_gemm(M_ROWS, XDBL_COLS, D_INNER, pAh, pAl, D_INNER,
                        pBh, pBl, XDBL_COLS, pxdbl, XDBL_COLS);
        }

        // 5. split delta slice + dt_proj weights; delta_raw = xdbl48 @ dt_w
        {
            split_xdbl48_kernel<<<(M_ROWS * DT_RANK + 255) / 256, 256>>>();
            int cnt = DT_RANK * D_INNER;
            split_arr_kernel<<<(cnt + 255) / 256, 256>>>(dtw, pBh, pBl, cnt);
            launch_gemm(M_ROWS, D_INNER, DT_RANK, pAh, pAl, DT_RANK,
                        pBh, pBl, D_INNER, pdelta, D_INNER);
        }

        // 6. softplus
        bias_softplus_kernel<<<(M_ROWS * D_INNER + 255) / 256, 256>>>(dtb);

        // 7. scan + gate -> split y into A buffers
        scan_kernel<<<B_SZ * D_INNER, 256>>>(al, dp);

        // 8. split out_proj weights; h = y @ out_w
        {
            int cnt = D_INNER * D_MODEL;
            split_arr_kernel<<<(cnt + 255) / 256, 256>>>(ow, pBh, pBl, cnt);
            launch_gemm(M_ROWS, D_MODEL, D_INNER, pAh, pAl, D_INNER,
                        pBh, pBl, D_MODEL, ph, D_MODEL);
        }

        // 9. residual
        residual_add_kernel<<<(M_ROWS * D_MODEL + 255) / 256, 256>>>();
    }

    // final rmsnorm -> split A; head GEMM
    rmsnorm_split_kernel<<<M_ROWS, 256>>>(px, norm_f_w);
    {
        int cnt = D_MODEL * N_MELS;
        split_arr_kernel<<<(cnt + 255) / 256, 256>>>(head_w, pBh, pBl, cnt);
        launch_gemm(M_ROWS, N_MELS, D_MODEL, pAh, pAl, D_MODEL,
                    pBh, pBl, N_MELS, out, N_MELS);
    }
}

// round 7
// speedup vs baseline: 1.7735x; 1.7735x over previous
#include <cuda_runtime.h>
#include <cuda_bf16.h>
#include <mma.h>
#include <math.h>
#include <stdint.h>

// ---------------- model constants ----------------
#define D_MODEL 768
#define N_LAYER 4
#define D_STATE 16
#define D_CONV 4
#define DT_RANK 48
#define D_INNER 1536
#define B_SZ 2
#define L_SEQ 1024
#define N_MELS 80
#define M_ROWS (B_SZ * L_SEQ)              // 2048
#define XDBL_COLS (DT_RANK + 2 * D_STATE)  // 80

// ---------------- scratch (device globals; no runtime alloc) ----------------
__device__ float g_x[M_ROWS * D_MODEL];        // residual stream
__device__ float g_h[M_ROWS * D_MODEL];        // out_proj result
__device__ float g_xz[M_ROWS * 2 * D_INNER];   // in_proj output
__device__ float g_xi[M_ROWS * D_INNER];       // conv+silu (u) fp32 for scan
__device__ float g_xdbl[M_ROWS * XDBL_COLS];   // x_proj output fp32
__device__ float g_delta[M_ROWS * D_INNER];    // softplus(dt)
__device__ float g_part[2 * M_ROWS * D_MODEL]; // split-K partials (3.15M floats)
// split-bf16 staging: A operands (activations) and B operands (weights)
__device__ __nv_bfloat16 g_Ah[M_ROWS * D_INNER];
__device__ __nv_bfloat16 g_Al[M_ROWS * D_INNER];
__device__ __nv_bfloat16 g_Bh[D_MODEL * 2 * D_INNER];
__device__ __nv_bfloat16 g_Bl[D_MODEL * 2 * D_INNER];

__device__ __forceinline__ void split_bf16(float v, __nv_bfloat16& hi, __nv_bfloat16& lo) {
    __nv_bfloat16 h = __float2bfloat16(v);
    float r = v - __bfloat162float(h);
    hi = h;
    lo = __float2bfloat16(r);
}

__device__ __forceinline__ void cpa16(uint32_t dst, const void* src, int valid) {
    asm volatile("cp.async.ca.shared.global [%0], [%1], 16, %2;"
                 :: "r"(dst), "l"(src), "r"(valid));
}

// ---------------- WMMA bf16 GEMM, pre-split inputs, cp.async pipeline -------
// C[M,N] = (Ah+Al)[M,K] * (Bh+Bl)[K,N]  (3-product split, fp32 accumulate)
// Block 128x128, BK=32, 8 warps (2x4), warp tile 64x32, 2 CTAs/SM.
// blockIdx.z = split-K slice: k range [z*kchunk, min(K,(z+1)*kchunk)),
// output written to C + z*M*ldc (partials reduced by reduce_splitk).
__global__ __launch_bounds__(256, 2)
void wmma_gemm_bf16(int M, int N, int K, int kchunk,
                    const __nv_bfloat16* __restrict__ Ah,
                    const __nv_bfloat16* __restrict__ Al, int lda,
                    const __nv_bfloat16* __restrict__ Bh,
                    const __nv_bfloat16* __restrict__ Bl, int ldb,
                    float* __restrict__ C, int ldc)
{
    using namespace nvcuda;
    constexpr int SA = 40;       // A row stride (bf16 elems), 80 B
    constexpr int SB = 136;      // B row stride, 272 B
    constexpr int OFF_AH = 0;
    constexpr int OFF_AL = 128 * SA * 2;            // 10240
    constexpr int OFF_BH = 2 * 128 * SA * 2;        // 20480
    constexpr int OFF_BL = OFF_BH + 32 * SB * 2;    // 29184
    constexpr int STAGE  = OFF_BL + 32 * SB * 2;    // 37888

    extern __shared__ char sm[];
    const uint32_t smb = (uint32_t)__cvta_generic_to_shared(sm);

    const int t    = threadIdx.x;
    const int warp = t >> 5;
    const int wm   = warp >> 2;
    const int wn   = warp & 3;
    const int row0 = blockIdx.y * 128;
    const int col0 = blockIdx.x * 128;

    const int k_lo = blockIdx.z * kchunk;
    const int k_hi = min(K, k_lo + kchunk);
    const int KT   = (k_hi - k_lo + 31) / 32;
    C += (long)blockIdx.z * M * ldc;

    wmma::fragment<wmma::accumulator, 16, 16, 16, float> acc[4][2];
#pragma unroll
    for (int i = 0; i < 4; i++)
#pragma unroll
        for (int j = 0; j < 2; j++) wmma::fill_fragment(acc[i][j], 0.0f);

    // per-thread loader coords
    const int arow = t >> 2,  ask = t & 3;     // A: 128 rows x 4 chunks of 8k
    const int brow = t >> 4,  bsk = t & 15;    // B: 16(+16) rows x 16 chunks of 8n

    auto issue_stage = [&](int st, int k0) {
        uint32_t base = smb + st * STAGE;
        // A tiles: 2 segments/thread (rows arow, arow covered once; 512 segs)
#pragma unroll
        for (int ss = 0; ss < 2; ss++) {
            int row = arow + ss * 64;          // wait: t>>2 in 0..63; two halves
            int kk = k0 + ask * 8;
            int valid = (k_hi - kk) * 2;
            valid = valid < 0 ? 0 : (valid > 16 ? 16 : valid);
            long srcoff = (long)(row0 + row) * lda + kk;
            cpa16(base + OFF_AH + row * (SA * 2) + ask * 16, Ah + srcoff, valid);
            cpa16(base + OFF_AL + row * (SA * 2) + ask * 16, Al + srcoff, valid);
        }
        // B tiles: 2 segments/thread (rows brow, brow+16)
#pragma unroll
        for (int ss = 0; ss < 2; ss++) {
            int row = brow + ss * 16;
            int nn = col0 + bsk * 8;
            int valid = (k0 + row < k_hi) ? (N - nn) * 2 : 0;
            valid = valid < 0 ? 0 : (valid > 16 ? 16 : valid);
            long srcoff = (long)(k0 + row) * ldb + nn;
            cpa16(base + OFF_BH + row * (SB * 2) + bsk * 16, Bh + srcoff, valid);
            cpa16(base + OFF_BL + row * (SB * 2) + bsk * 16, Bl + srcoff, valid);
        }
        asm volatile("cp.async.commit_group;" ::: "memory");
    };

    issue_stage(0, k_lo);

    for (int kt = 0; kt < KT; kt++) {
        asm volatile("cp.async.wait_group 0;" ::: "memory");
        __syncthreads();   // stage kt visible; all threads done with kt-1 buffer
        if (kt + 1 < KT) issue_stage((kt + 1) & 1, k_lo + (kt + 1) * 32);

        const char* buf = sm + (kt & 1) * STAGE;
        const __nv_bfloat16* pAh = (const __nv_bfloat16*)(buf + OFF_AH);
        const __nv_bfloat16* pAl = (const __nv_bfloat16*)(buf + OFF_AL);
        const __nv_bfloat16* pBh = (const __nv_bfloat16*)(buf + OFF_BH);
        const __nv_bfloat16* pBl = (const __nv_bfloat16*)(buf + OFF_BL);

#pragma unroll
        for (int ks = 0; ks < 2; ks++) {
            wmma::fragment<wmma::matrix_b, 16, 16, 16, __nv_bfloat16, wmma::row_major> fbh[2], fbl[2];
#pragma unroll
            for (int j = 0; j < 2; j++) {
                wmma::load_matrix_sync(fbh[j], pBh + (ks * 16) * SB + wn * 32 + j * 16, SB);
                wmma::load_matrix_sync(fbl[j], pBl + (ks * 16) * SB + wn * 32 + j * 16, SB);
            }
#pragma unroll
            for (int i = 0; i < 4; i++) {
                wmma::fragment<wmma::matrix_a, 16, 16, 16, __nv_bfloat16, wmma::row_major> fah, fal;
                wmma::load_matrix_sync(fah, pAh + (wm * 64 + i * 16) * SA + ks * 16, SA);
                wmma::load_matrix_sync(fal, pAl + (wm * 64 + i * 16) * SA + ks * 16, SA);
                // alternate accumulators to break same-acc RAW chains
#pragma unroll
                for (int j = 0; j < 2; j++) wmma::mma_sync(acc[i][j], fah, fbh[j], acc[i][j]);
#pragma unroll
                for (int j = 0; j < 2; j++) wmma::mma_sync(acc[i][j], fah, fbl[j], acc[i][j]);
#pragma unroll
                for (int j = 0; j < 2; j++) wmma::mma_sync(acc[i][j], fal, fbh[j], acc[i][j]);
            }
        }
    }

    // ---- epilogue ----
#pragma unroll
    for (int i = 0; i < 4; i++)
#pragma unroll
        for (int j = 0; j < 2; j++) {
            int gm = row0 + wm * 64 + i * 16;
            int gn = col0 + wn * 32 + j * 16;
            if (gn + 16 <= N)
                wmma::store_matrix_sync(C + (long)gm * ldc + gn, acc[i][j],
                                        ldc, wmma::mem_row_major);
        }
}

// sum split-K partials: outp[i] = sum_s part[s*count + i]
__global__ void reduce_splitk(const float* __restrict__ part,
                              float* __restrict__ outp, int count, int splits)
{
    int i = blockIdx.x * blockDim.x + threadIdx.x;
    if (i >= count) return;
    float s = 0.0f;
    for (int k = 0; k < splits; k++) s += part[(long)k * count + i];
    outp[i] = s;
}

// ---------------- split helpers ----------------
__global__ void split_arr_kernel(const float* __restrict__ in,
                                 __nv_bfloat16* __restrict__ hi,
                                 __nv_bfloat16* __restrict__ lo, int count)
{
    int i = blockIdx.x * blockDim.x + threadIdx.x;
    if (i < count) {
        __nv_bfloat16 h, l;
        split_bf16(in[i], h, l);
        hi[i] = h; lo[i] = l;
    }
}

__global__ void split_xdbl48_kernel(void)
{
    int i = blockIdx.x * blockDim.x + threadIdx.x;
    if (i < M_ROWS * DT_RANK) {
        int r = i / DT_RANK, c = i % DT_RANK;
        __nv_bfloat16 h, l;
        split_bf16(g_xdbl[r * XDBL_COLS + c], h, l);
        g_Ah[i] = h; g_Al[i] = l;
    }
}

// ---------------- elementwise / small kernels ----------------
__global__ void embed_kernel(const int* __restrict__ ids,
                             const float* __restrict__ emb)
{
    int row = blockIdx.x;
    int id = ids[row];
    for (int c = threadIdx.x; c < D_MODEL; c += blockDim.x)
        g_x[row * D_MODEL + c] = emb[(long)id * D_MODEL + c];
}

__global__ void rmsnorm_split_kernel(const float* __restrict__ x,
                                     const float* __restrict__ w)
{
    __shared__ float red[256];
    int row = blockIdx.x;
    const float* xr = x + row * D_MODEL;
    float s = 0.0f;
    for (int c = threadIdx.x; c < D_MODEL; c += blockDim.x) {
        float v = xr[c];
        s += v * v;
    }
    red[threadIdx.x] = s;
    __syncthreads();
    for (int off = 128; off > 0; off >>= 1) {
        if (threadIdx.x < off) red[threadIdx.x] += red[threadIdx.x + off];
        __syncthreads();
    }
    float scale = rsqrtf(red[0] / (float)D_MODEL + 1e-5f);
    for (int c = threadIdx.x; c < D_MODEL; c += blockDim.x) {
        __nv_bfloat16 h, l;
        split_bf16(xr[c] * scale * w[c], h, l);
        g_Ah[row * D_MODEL + c] = h;
        g_Al[row * D_MODEL + c] = l;
    }
}

__global__ void conv_silu_kernel(const float* __restrict__ cw,
                                 const float* __restrict__ cb)
{
    int i = blockIdx.x * blockDim.x + threadIdx.x;
    if (i >= M_ROWS * D_INNER) return;
    int row = i / D_INNER;
    int d = i % D_INNER;
    int b = row / L_SEQ;
    int l = row % L_SEQ;
    float acc = cb[d];
#pragma unroll
    for (int k = 0; k < D_CONV; k++) {
        int ll = l + k - (D_CONV - 1);
        if (ll >= 0)
            acc = fmaf(g_xz[(long)(b * L_SEQ + ll) * (2 * D_INNER) + d],
                       cw[d * D_CONV + k], acc);
    }
    float sg = 1.0f / (1.0f + __expf(-acc));
    float v = acc * sg;
    g_xi[i] = v;
    __nv_bfloat16 h, lo;
    split_bf16(v, h, lo);
    g_Ah[i] = h; g_Al[i] = lo;
}

__global__ void bias_softplus_kernel(const float* __restrict__ bias)
{
    int i = blockIdx.x * blockDim.x + threadIdx.x;
    if (i >= M_ROWS * D_INNER) return;
    int d = i % D_INNER;
    float v = g_delta[i] + bias[d];
    float r = (v > 30.0f) ? v : log1pf(__expf(v));
    g_delta[i] = r;
}

__global__ void residual_add_kernel(void)
{
    int i = blockIdx.x * blockDim.x + threadIdx.x;
    if (i < M_ROWS * D_MODEL) g_x[i] += g_h[i];
}

// ---------------- selective scan (chunked parallel prefix) ----------------
__global__ __launch_bounds__(256)
void scan_kernel(const float* __restrict__ A_log,
                 const float* __restrict__ Dp)
{
    __shared__ float sTot[16][17];
    __shared__ float pTot[16][17];

    const int tid = threadIdx.x;
    const int c = tid >> 4;
    const int n = tid & 15;
    const int bd = blockIdx.x;
    const int b = bd / D_INNER;
    const int d = bd % D_INNER;

    const float A_dn = -__expf(A_log[d * D_STATE + n]);
    const int CH = L_SEQ / 16;
    const long rowbase = (long)b * L_SEQ + (long)c * CH;
    const int lg0 = c * CH;

    float sloc = 0.0f;
    for (int i = 0; i < CH; i++) {
        float dt = g_delta[(rowbase + i) * D_INNER + d];
        float a = fmaxf(dt * A_dn, -20.0f);
        if (lg0 + i > 0) sloc += a;
    }
    sTot[n][c] = sloc;
    __syncthreads();
    float soff = 0.0f;
#pragma unroll
    for (int cc = 0; cc < 16; cc++)
        if (cc < c) soff += sTot[n][cc];

    sloc = 0.0f;
    float Ploc = 0.0f;
    for (int i = 0; i < CH; i++) {
        long row = rowbase + i;
        float dt = g_delta[row * D_INNER + d];
        float u  = g_xi[row * D_INNER + d];
        float Bn = g_xdbl[row * XDBL_COLS + DT_RANK + n];
        float a = fmaxf(dt * A_dn, -20.0f);
        if (lg0 + i > 0) sloc += a;
        float e = __expf(soff + sloc);
        Ploc += __fdividef(dt * u * Bn, e + 1e-12f);
    }
    pTot[n][c] = Ploc;
    __syncthreads();
    float Poff = 0.0f;
#pragma unroll
    for (int cc = 0; cc < 16; cc++)
        if (cc < c) Poff += pTot[n][cc];

    const float Dd = Dp[d];

    sloc = 0.0f;
    Ploc = 0.0f;
    for (int i = 0; i < CH; i++) {
        long row = rowbase + i;
        float dt = g_delta[row * D_INNER + d];
        float u  = g_xi[row * D_INNER + d];
        float Bn = g_xdbl[row * XDBL_COLS + DT_RANK + n];
        float Cn = g_xdbl[row * XDBL_COLS + DT_RANK + D_STATE + n];
        float a = fmaxf(dt * A_dn, -20.0f);
        if (lg0 + i > 0) sloc += a;
        float e = __expf(soff + sloc);
        Ploc += __fdividef(dt * u * Bn, e + 1e-12f);
        float x = (Poff + Ploc) * e;
        float yp = x * Cn;
#pragma unroll
        for (int off = 8; off >= 1; off >>= 1)
            yp += __shfl_xor_sync(0xffffffffu, yp, off, 16);
        if (n == 0) {
            float r = g_xz[row * (2 * D_INNER) + D_INNER + d];
            float sr = r / (1.0f + __expf(-r));
            float yv = (yp + u * Dd) * sr;
            __nv_bfloat16 h, l;
            split_bf16(yv, h, l);
            g_Ah[row * D_INNER + d] = h;
            g_Al[row * D_INNER + d] = l;
        }
    }
}

// ---------------- host side ----------------
static inline void* sym(const void* s)
{
    void* p = nullptr;
    cudaGetSymbolAddress(&p, s);
    return p;
}

#define GEMM_SMEM (2 * 37888)

static void launch_gemm(int M, int N, int K, int splits,
                        const __nv_bfloat16* Ah, const __nv_bfloat16* Al, int lda,
                        const __nv_bfloat16* Bh, const __nv_bfloat16* Bl, int ldb,
                        float* C, int ldc)
{
    int kchunk = (K + splits - 1) / splits;
    dim3 grid((N + 127) / 128, M / 128, splits);
    wmma_gemm_bf16<<<grid, 256, GEMM_SMEM>>>(M, N, K, kchunk,
                                             Ah, Al, lda, Bh, Bl, ldb, C, ldc);
}

extern "C" void kernel_launch(void* const* d_in, const int* in_sizes, int n_in,
                              void* d_out, int out_size)
{
    const int*   input_ids = (const int*)  d_in[0];
    const float* embedding = (const float*)d_in[1];
    const float* rms_w     = (const float*)d_in[2];
    const float* in_proj_w = (const float*)d_in[3];
    const float* conv_w    = (const float*)d_in[4];
    const float* conv_b    = (const float*)d_in[5];
    const float* x_proj_w  = (const float*)d_in[6];
    const float* dt_proj_w = (const float*)d_in[7];
    const float* dt_proj_b = (const float*)d_in[8];
    const float* A_log     = (const float*)d_in[9];
    const float* D_param   = (const float*)d_in[10];
    const float* out_proj_w= (const float*)d_in[11];
    const float* norm_f_w  = (const float*)d_in[12];
    const float* head_w    = (const float*)d_in[13];
    float* out = (float*)d_out;

    float* px     = (float*)sym(g_x);
    float* pxz    = (float*)sym(g_xz);
    float* pxdbl  = (float*)sym(g_xdbl);
    float* pdelta = (float*)sym(g_delta);
    float* ph     = (float*)sym(g_h);
    float* ppart  = (float*)sym(g_part);
    __nv_bfloat16* pAh = (__nv_bfloat16*)sym(g_Ah);
    __nv_bfloat16* pAl = (__nv_bfloat16*)sym(g_Al);
    __nv_bfloat16* pBh = (__nv_bfloat16*)sym(g_Bh);
    __nv_bfloat16* pBl = (__nv_bfloat16*)sym(g_Bl);

    cudaFuncSetAttribute(wmma_gemm_bf16,
                         cudaFuncAttributeMaxDynamicSharedMemorySize, GEMM_SMEM);

    embed_kernel<<<M_ROWS, 256>>>(input_ids, embedding);

    for (int i = 0; i < N_LAYER; i++) {
        const float* rw  = rms_w     + (long)i * D_MODEL;
        const float* iw  = in_proj_w + (long)i * D_MODEL * 2 * D_INNER;
        const float* cw  = conv_w    + (long)i * D_INNER * D_CONV;
        const float* cb  = conv_b    + (long)i * D_INNER;
        const float* xpw = x_proj_w  + (long)i * D_INNER * XDBL_COLS;
        const float* dtw = dt_proj_w + (long)i * DT_RANK * D_INNER;
        const float* dtb = dt_proj_b + (long)i * D_INNER;
        const float* al  = A_log     + (long)i * D_INNER * D_STATE;
        const float* dp  = D_param   + (long)i * D_INNER;
        const float* ow  = out_proj_w+ (long)i * D_INNER * D_MODEL;

        // 1. rmsnorm -> split A
        rmsnorm_split_kernel<<<M_ROWS, 256>>>(px, rw);

        // 2. in_proj: xz = h @ in_w   [2048 x 3072 x 768]
        {
            int cnt = D_MODEL * 2 * D_INNER;
            split_arr_kernel<<<(cnt + 255) / 256, 256>>>(iw, pBh, pBl, cnt);
            launch_gemm(M_ROWS, 2 * D_INNER, D_MODEL, 1, pAh, pAl, D_MODEL,
                        pBh, pBl, 2 * D_INNER, pxz, 2 * D_INNER);
        }

        // 3. conv+silu
        conv_silu_kernel<<<(M_ROWS * D_INNER + 255) / 256, 256>>>(cw, cb);

        // 4. x_proj (split-K 8): x_dbl = xi @ xp_w   [2048 x 80 x 1536]
        {
            int cnt = D_INNER * XDBL_COLS;
            split_arr_kernel<<<(cnt + 255) / 256, 256>>>(xpw, pBh, pBl, cnt);
            launch_gemm(M_ROWS, XDBL_COLS, D_INNER, 8, pAh, pAl, D_INNER,
                        pBh, pBl, XDBL_COLS, ppart, XDBL_COLS);
            int rcount = M_ROWS * XDBL_COLS;
            reduce_splitk<<<(rcount + 255) / 256, 256>>>(ppart, pxdbl, rcount, 8);
        }

        // 5. dt_proj: delta_raw = xdbl48 @ dt_w   [2048 x 1536 x 48]
        {
            split_xdbl48_kernel<<<(M_ROWS * DT_RANK + 255) / 256, 256>>>();
            int cnt = DT_RANK * D_INNER;
            split_arr_kernel<<<(cnt + 255) / 256, 256>>>(dtw, pBh, pBl, cnt);
            launch_gemm(M_ROWS, D_INNER, DT_RANK, 1, pAh, pAl, DT_RANK,
                        pBh, pBl, D_INNER, pdelta, D_INNER);
        }

        // 6. softplus
        bias_softplus_kernel<<<(M_ROWS * D_INNER + 255) / 256, 256>>>(dtb);

        // 7. scan + gate -> split y
        scan_kernel<<<B_SZ * D_INNER, 256>>>(al, dp);

        // 8. out_proj (split-K 2): h = y @ out_w   [2048 x 768 x 1536]
        {
            int cnt = D_INNER * D_MODEL;
            split_arr_kernel<<<(cnt + 255) / 256, 256>>>(ow, pBh, pBl, cnt);
            launch_gemm(M_ROWS, D_MODEL, D_INNER, 2, pAh, pAl, D_INNER,
                        pBh, pBl, D_MODEL, ppart, D_MODEL);
            int rcount = M_ROWS * D_MODEL;
            reduce_splitk<<<(rcount + 255) / 256, 256>>>(ppart, ph, rcount, 2);
        }

        // 9. residual
        residual_add_kernel<<<(M_ROWS * D_MODEL + 255) / 256, 256>>>();
    }

    // final rmsnorm + head (split-K 4)
    rmsnorm_split_kernel<<<M_ROWS, 256>>>(px, norm_f_w);
    {
        int cnt = D_MODEL * N_MELS;
        split_arr_kernel<<<(cnt + 255) / 256, 256>>>(head_w, pBh, pBl, cnt);
        launch_gemm(M_ROWS, N_MELS, D_MODEL, 4, pAh, pAl, D_MODEL,
                    pBh, pBl, N_MELS, ppart, N_MELS);
        int rcount = M_ROWS * N_MELS;
        reduce_splitk<<<(rcount + 255) / 256, 256>>>(ppart, out, rcount, 4);
    }
}